// round 15
// baseline (speedup 1.0000x reference)
#include <cuda_runtime.h>
#include <math.h>

#define N_NODES 15
#define EMBED   2048
#define F1      1024
#define F2      512
#define NE      120
#define H1N     480
#define H2N     1920
#define HN      (N_NODES*EMBED)   // 30720

// ---------- scratch (device globals) ----------
__device__ float g_h2[H2N];
__device__ float g_H[HN];
__device__ float g_HW1[N_NODES*F1];
__device__ float g_X1[N_NODES*F1];
__device__ float g_HW2[N_NODES*F2];
__device__ float g_X2[N_NODES*F2];
__device__ float g_m[F2];
__device__ float g_ctx[F2];
__device__ int   g_cnt1[8], g_cnt2[4];
__device__ int   g_done2, g_done3;
__device__ int   g_flag2, g_flag3;
__device__ int   g_t1f[8];             // per-gcn0-tile "X1 ready" flags
__device__ int   g_tile;               // work-stealing ticket for mlp3

// =====================================================================
// K_PRE (512 thr): blocks 0..59: MLP1 (1 wave) + MLP2 (32 cols x 16 kgrp,
//                  2 waves of 15, fully coalesced).  blocks 60..147: inits.
// =====================================================================
__global__ void __launch_bounds__(512) k_pre(
    const float* __restrict__ f,  const float* __restrict__ W1, const float* __restrict__ b1,
    const float* __restrict__ W2, const float* __restrict__ b2, const float* __restrict__ b3) {
    int bx = blockIdx.x, t = threadIdx.x;
    if (bx < 60) {
        __shared__ float sf[N_NODES];
        __shared__ float sh1[H1N];
        __shared__ float red[16][32];
        if (t < N_NODES) sf[t] = f[t];
        __syncthreads();
        if (t < H1N) {                     // MLP1: one 15-deep wave
            float wv[N_NODES];
#pragma unroll
            for (int i = 0; i < N_NODES; i++) wv[i] = __ldg(&W1[i * H1N + t]);
            float a = b1[t];
#pragma unroll
            for (int i = 0; i < N_NODES; i++) a += sf[i] * wv[i];
            sh1[t] = fmaxf(a, 0.f);
        }
        __syncthreads();
        // MLP2: 32 cols x 16 kgrps of 30 -> 2 waves of 15, 128B-coalesced
        int col = bx * 32 + (t & 31);
        int kg  = t >> 5;                  // 0..15
        int k0  = kg * 30;
        float a = 0.f;
#pragma unroll
        for (int kb = 0; kb < 30; kb += 15) {
            float wv[15];
#pragma unroll
            for (int u = 0; u < 15; u++) wv[u] = __ldg(&W2[(size_t)(k0 + kb + u) * H2N + col]);
#pragma unroll
            for (int u = 0; u < 15; u++) a += sh1[k0 + kb + u] * wv[u];
        }
        red[kg][t & 31] = a;
        __syncthreads();
        if (t < 32) {
            int c = bx * 32 + t;
            float v = b2[c];
#pragma unroll
            for (int s2 = 0; s2 < 16; s2++) v += red[s2][t];
            g_h2[c] = fmaxf(v, 0.f);
        }
    } else {
        int gt = (bx - 60) * 512 + t;      // 0 .. 45055
        if (gt < HN)            g_H[gt]   = b3[gt];
        if (gt < N_NODES * F1)  g_HW1[gt] = 0.f;
        if (gt < N_NODES * F2)  g_HW2[gt] = 0.f;
        if (gt < F2)            g_ctx[gt] = 0.f;
        if (gt < 8)  { g_cnt1[gt] = 0; g_t1f[gt] = 0; }
        if (gt < 4)    g_cnt2[gt] = 0;
        if (gt == 0) { g_done2 = 0; g_done3 = 0;
                       g_flag2 = 0; g_flag3 = 0; g_tile = 0; }
    }
}

// =====================================================================
// K_MLP3: sparse relu(h2) @ W3 stream with WORK STEALING over 960 tiles.
// 888 blocks x 128 thr; each steals (x,y) tiles until the ticket runs out.
// =====================================================================
__global__ void __launch_bounds__(128) k_mlp3(const float4* __restrict__ W3v) {
    __shared__ float sval[128];
    __shared__ int   sidx[128];
    __shared__ int   scnt;
    __shared__ int   stile;
    int t = threadIdx.x;
    for (;;) {
        __syncthreads();                    // prior iteration's smem reads done
        if (t == 0) stile = atomicAdd(&g_tile, 1);
        __syncthreads();
        int tile = stile;
        if (tile >= 960) break;
        int x = tile % 60;                  // 60 col-groups of 128 float4
        int y = tile / 60;                  // 16 k-segments of 120
        int k0 = y * 120;

        if (t == 0) scnt = 0;
        __syncthreads();
        if (t < 120) {
            float h = g_h2[k0 + t];
            if (h > 0.f) {
                int p = atomicAdd(&scnt, 1);
                sidx[p] = t; sval[p] = h;
            }
        }
        __syncthreads();
        int cnt = scnt;
        int pad = (cnt + 7) & ~7;
        if (t < 8 && cnt + t < pad) { sidx[cnt + t] = sidx[0]; sval[cnt + t] = 0.f; }
        __syncthreads();

        int c = x * 128 + t;
        const float4* base = W3v + (size_t)k0 * 7680 + c;
        float4 acc = make_float4(0.f, 0.f, 0.f, 0.f);
        for (int q = 0; q < cnt; q += 8) {
            int   id[8]; float hv[8]; float4 w[8];
#pragma unroll
            for (int u = 0; u < 8; u++) { id[u] = sidx[q + u]; hv[u] = sval[q + u]; }
#pragma unroll
            for (int u = 0; u < 8; u++) w[u] = __ldcs(base + (size_t)id[u] * 7680);
#pragma unroll
            for (int u = 0; u < 8; u++) {
                acc.x += hv[u] * w[u].x; acc.y += hv[u] * w[u].y;
                acc.z += hv[u] * w[u].z; acc.w += hv[u] * w[u].w;
            }
        }
        float* o = g_H + 4 * c;
        atomicAdd(o + 0, acc.x); atomicAdd(o + 1, acc.y);
        atomicAdd(o + 2, acc.z); atomicAdd(o + 3, acc.w);
    }
}

// =====================================================================
// tail helpers
// =====================================================================
__device__ __forceinline__ void spin_flag(int* flag, int t) {
    if (t == 0) { while (*(volatile int*)flag == 0) __nanosleep(64); }
    __syncthreads();
    __threadfence();
}

// GEMM slice (512 thr: 128 cols x 4 sub-k groups) + last-block aggregation.
template <int L>
__device__ __forceinline__ void gcn_phase(int x, int y, int t,
                                          const float* __restrict__ W,
                                          const float* __restrict__ bias,
                                          const int* __restrict__ eidx) {
    constexpr int K     = (L == 0) ? 2048 : 1024;
    constexpr int N     = (L == 0) ? 1024 : 512;
    constexpr int KTILE = (L == 0) ? 128 : 64;
    constexpr int QK    = KTILE / 4;
    constexpr int NY    = 16;
    const float* X  = (L == 0) ? g_H  : g_X1;
    float* OUT      = (L == 0) ? g_HW1 : g_HW2;
    float* XO       = (L == 0) ? g_X1 : g_X2;
    int*   cnt      = (L == 0) ? g_cnt1 : g_cnt2;

    __shared__ float4 Xt4[N_NODES * 32];
    __shared__ float  Sred[3][N_NODES][128];
    float* Xt = (float*)Xt4;
    int k0 = y * KTILE;
    for (int idx = t; idx < N_NODES * (KTILE / 4); idx += 512) {
        int i = idx / (KTILE / 4), c = idx % (KTILE / 4);
        Xt4[i * 32 + c] = *(const float4*)(X + (size_t)i * K + k0 + 4 * c);
    }
    __syncthreads();

    int g  = t >> 7;
    int jt = t & 127;
    int j  = x * 128 + jt;
    const float* wp = W + (size_t)(k0 + g * QK) * N + j;
    float acc[N_NODES];
#pragma unroll
    for (int i = 0; i < N_NODES; i++) acc[i] = 0.f;
#pragma unroll
    for (int kb = 0; kb < QK; kb += 16) {
        float wv[16];
#pragma unroll
        for (int u = 0; u < 16; u++) wv[u] = __ldg(wp + (size_t)(kb + u) * N);
#pragma unroll
        for (int u = 0; u < 16; u++) {
            const float* xr = &Xt[g * QK + kb + u];
#pragma unroll
            for (int i = 0; i < N_NODES; i++) acc[i] += xr[i * 128] * wv[u];
        }
    }
    __syncthreads();
    if (g > 0) {
#pragma unroll
        for (int i = 0; i < N_NODES; i++) Sred[g - 1][i][jt] = acc[i];
    }
    __syncthreads();
    if (g == 0) {
#pragma unroll
        for (int i = 0; i < N_NODES; i++)
            atomicAdd(&OUT[i * N + j],
                      acc[i] + Sred[0][i][jt] + Sred[1][i][jt] + Sred[2][i][jt]);
    }

    __threadfence();
    __syncthreads();
    __shared__ int isLast;
    if (t == 0) isLast = (atomicAdd(&cnt[x], 1) == NY - 1);
    __syncthreads();
    if (!isLast) return;

    __shared__ int   se[NE], de[NE];
    __shared__ float degs[N_NODES], dinv[N_NODES], nrm[NE];
    __shared__ float hws[N_NODES][128];
    __shared__ float outs[N_NODES][128];
    if (t < NE) { se[t] = eidx[t]; de[t] = eidx[NE + t]; }
    if (t < N_NODES) degs[t] = 1.f;
    __syncthreads();
    if (t < NE) atomicAdd(&degs[de[t]], 1.f);
    __syncthreads();
    if (t < N_NODES) dinv[t] = rsqrtf(degs[t]);
    __syncthreads();
    if (t < NE) nrm[t] = dinv[se[t]] * dinv[de[t]];
    if (t < 128) {
#pragma unroll
        for (int i = 0; i < N_NODES; i++) hws[i][t] = __ldcg(&OUT[i * N + x * 128 + t]);
    }
    __syncthreads();
    if (t < 128) {
        int jj = x * 128 + t;
#pragma unroll
        for (int i = 0; i < N_NODES; i++) outs[i][t] = hws[i][t] * dinv[i] * dinv[i];
        for (int e = 0; e < NE; e++)
            outs[de[e]][t] += hws[se[e]][t] * nrm[e];

        float b = bias[jj];
        float s = 0.f;
#pragma unroll
        for (int i = 0; i < N_NODES; i++) {
            float v = outs[i][t] + b;
            if (L == 0) v = fmaxf(v, 0.f);
            XO[i * N + jj] = v;
            s += v;
        }
        if (L == 1) g_m[jj] = s * (1.f / 15.f);
    }
    __threadfence();
    __syncthreads();
    if (t == 0) {
        if (L == 0) {
            atomicExch(&g_t1f[x], 1);          // per-tile X1-ready flag
        } else {
            if (atomicAdd(&g_done2, 1) == 3) atomicExch(&g_flag2, 1);
        }
    }
}

// =====================================================================
// K_TAIL (512 thr): gcn0 -> (per-tile flags) gcn1 -> ctx -> final
// =====================================================================
__global__ void __launch_bounds__(512) k_tail(
    const float* __restrict__ gW1, const float* __restrict__ gb1,
    const float* __restrict__ gW2, const float* __restrict__ gb2,
    const float* __restrict__ attW,
    const float* __restrict__ fcW, const float* __restrict__ fcb,
    const int* __restrict__ eidx, const float* __restrict__ target,
    float* __restrict__ out) {
    int b = blockIdx.x, t = threadIdx.x;

    // ---- phase 1: GCN layer 0 (128 blocks: 8 x-tiles x 16 ksplit) ----
    gcn_phase<0>(b & 7, b >> 3, t, gW1, gb1, eidx);
    if (b >= 64) return;

    // ---- phase 2: GCN layer 1 (64 blocks: 4 x x 16 y); each y-split
    //      needs only gcn0 tile (y>>1) -> per-tile spin, early start ----
    {
        int y = b >> 2;
        spin_flag(&g_t1f[y >> 1], t);
        gcn_phase<1>(b & 3, y, t, gW2, gb2, eidx);
    }
    if (b >= 16) return;

    // ---- phase 3: ctx = m @ attW (16 blocks, full 512-col rows) ----
    spin_flag(&g_flag2, t);
    {
        __shared__ float sm[32];
        int k0 = b * 32;
        if (t < 32) sm[t] = g_m[k0 + t];
        __syncthreads();
        float a = 0.f;
#pragma unroll
        for (int kb = 0; kb < 32; kb += 16) {
            float wv[16];
#pragma unroll
            for (int u = 0; u < 16; u++) wv[u] = __ldg(&attW[(size_t)(k0 + kb + u) * F2 + t]);
#pragma unroll
            for (int u = 0; u < 16; u++) a += sm[kb + u] * wv[u];
        }
        atomicAdd(&g_ctx[t], a);
        __threadfence();
        __syncthreads();
        if (t == 0) {
            if (atomicAdd(&g_done3, 1) == 15) atomicExch(&g_flag3, 1);
        }
    }
    if (b != 0) return;

    // ---- phase 4: attention pool + fc + softmax + loss (512 thr) ----
    spin_flag(&g_flag3, t);
    {
        __shared__ float ctx_s[F2];
        __shared__ float sc[N_NODES];
        __shared__ float lg[3];
        ctx_s[t] = tanhf(g_ctx[t]);
        if (t < 3) lg[t] = fcb[t];
        __syncthreads();

        int w = t >> 5, l = t & 31;
        if (w < N_NODES) {
            float v = 0.f;
#pragma unroll
            for (int q = 0; q < 16; q++) {
                int j = l + 32 * q;
                v += g_X2[w * F2 + j] * ctx_s[j];
            }
#pragma unroll
            for (int o = 16; o > 0; o >>= 1) v += __shfl_xor_sync(0xffffffffu, v, o);
            if (l == 0) sc[w] = 1.f / (1.f + expf(-v));
        }
        __syncthreads();

        float rep = 0.f;
#pragma unroll
        for (int i = 0; i < N_NODES; i++) rep += g_X2[i * F2 + t] * sc[i];
        float p0 = rep * fcW[t * 3 + 0];
        float p1 = rep * fcW[t * 3 + 1];
        float p2 = rep * fcW[t * 3 + 2];
#pragma unroll
        for (int o = 16; o > 0; o >>= 1) {
            p0 += __shfl_xor_sync(0xffffffffu, p0, o);
            p1 += __shfl_xor_sync(0xffffffffu, p1, o);
            p2 += __shfl_xor_sync(0xffffffffu, p2, o);
        }
        if (l == 0) { atomicAdd(&lg[0], p0); atomicAdd(&lg[1], p1); atomicAdd(&lg[2], p2); }
        __syncthreads();

        if (t == 0) {
            float l0 = lg[0], l1 = lg[1], l2 = lg[2];
            float mx = fmaxf(l0, fmaxf(l1, l2));
            float e0 = expf(l0 - mx), e1 = expf(l1 - mx), e2 = expf(l2 - mx);
            float s = e0 + e1 + e2;
            float t0 = target[0], t1 = target[1], t2 = target[2];
            int cls = 0; float tm = t0;
            if (t1 > tm) { tm = t1; cls = 1; }
            if (t2 > tm) { tm = t2; cls = 2; }
            float lcls = (cls == 0) ? l0 : ((cls == 1) ? l1 : l2);
            out[0] = -(lcls - mx - logf(s));
            out[1] = e0 / s; out[2] = e1 / s; out[3] = e2 / s;
        }
    }
}

// ---------- host ----------
extern "C" void kernel_launch(void* const* d_in, const int* in_sizes, int n_in,
                              void* d_out, int out_size) {
    const float* f      = (const float*)d_in[0];
    const int*   eidx   = (const int*)  d_in[1];
    const float* target = (const float*)d_in[2];
    const float* W1     = (const float*)d_in[3];
    const float* b1     = (const float*)d_in[4];
    const float* W2     = (const float*)d_in[5];
    const float* b2     = (const float*)d_in[6];
    const float* W3     = (const float*)d_in[7];
    const float* b3     = (const float*)d_in[8];
    const float* gW1    = (const float*)d_in[9];
    const float* gb1    = (const float*)d_in[10];
    const float* gW2    = (const float*)d_in[11];
    const float* gb2    = (const float*)d_in[12];
    const float* attW   = (const float*)d_in[13];
    const float* fcW    = (const float*)d_in[14];
    const float* fcb    = (const float*)d_in[15];
    float* out = (float*)d_out;

    k_pre <<<148, 512>>>(f, W1, b1, W2, b2, b3);
    k_mlp3<<<888, 128>>>((const float4*)W3);
    k_tail<<<128, 512>>>(gW1, gb1, gW2, gb2, attW, fcW, fcb, eidx, target, out);
}

// round 16
// speedup vs baseline: 1.2063x; 1.2063x over previous
#include <cuda_runtime.h>
#include <math.h>

#define N_NODES 15
#define EMBED   2048
#define F1      1024
#define F2      512
#define NE      120
#define H1N     480
#define H2N     1920
#define HN      (N_NODES*EMBED)   // 30720

// ---------- scratch (device globals) ----------
__device__ float g_h2[H2N];
__device__ float g_H[HN];
__device__ float g_HW1[N_NODES*F1];
__device__ float g_X1[N_NODES*F1];
__device__ float g_HW2[N_NODES*F2];
__device__ float g_X2[N_NODES*F2];
__device__ float g_m[F2];
__device__ float g_ctx[F2];
__device__ int   g_cnt1[8], g_cnt2[4];
__device__ int   g_done1, g_done2, g_done3;
__device__ int   g_flag1, g_flag2, g_flag3;

// =====================================================================
// K_PRE: blocks 0..119: MLP1 (redundant, smem) + MLP2 (16 cols x 16 kgrp)
//        blocks 120..147: accumulator inits + sync-state reset
// (verbatim R11 champion)
// =====================================================================
__global__ void __launch_bounds__(256) k_pre(
    const float* __restrict__ f,  const float* __restrict__ W1, const float* __restrict__ b1,
    const float* __restrict__ W2, const float* __restrict__ b2, const float* __restrict__ b3) {
    int bx = blockIdx.x, t = threadIdx.x;
    if (bx < 120) {
        __shared__ float sf[N_NODES];
        __shared__ float sh1[H1N];
        __shared__ float red[16][16];
        if (t < N_NODES) sf[t] = f[t];
        __syncthreads();
        for (int j = t; j < H1N; j += 256) {
            float wv[N_NODES];
#pragma unroll
            for (int i = 0; i < N_NODES; i++) wv[i] = __ldg(&W1[i * H1N + j]);
            float a = b1[j];
#pragma unroll
            for (int i = 0; i < N_NODES; i++) a += sf[i] * wv[i];
            sh1[j] = fmaxf(a, 0.f);
        }
        __syncthreads();
        int col = bx * 16 + (t & 15);
        int kg  = t >> 4;                 // 16 k-groups of 30
        int k0  = kg * 30;
        float a = 0.f;
#pragma unroll
        for (int kb = 0; kb < 30; kb += 15) {
            float wv[15];
#pragma unroll
            for (int u = 0; u < 15; u++) wv[u] = __ldg(&W2[(size_t)(k0 + kb + u) * H2N + col]);
#pragma unroll
            for (int u = 0; u < 15; u++) a += sh1[k0 + kb + u] * wv[u];
        }
        red[kg][t & 15] = a;
        __syncthreads();
        if (t < 16) {
            int c = bx * 16 + t;
            float v = b2[c];
#pragma unroll
            for (int s2 = 0; s2 < 16; s2++) v += red[s2][t];
            g_h2[c] = fmaxf(v, 0.f);
        }
    } else {
        int gt = (bx - 120) * 256 + t;    // 0 .. 7167
        const int GS = 28 * 256;
#pragma unroll 5
        for (int i = gt; i < HN; i += GS)           g_H[i]   = b3[i];
#pragma unroll 3
        for (int i = gt; i < N_NODES * F1; i += GS) g_HW1[i] = 0.f;
#pragma unroll 2
        for (int i = gt; i < N_NODES * F2; i += GS) g_HW2[i] = 0.f;
        if (gt < F2) g_ctx[gt] = 0.f;
        if (gt < 8)  g_cnt1[gt] = 0;
        if (gt < 4)  g_cnt2[gt] = 0;
        if (gt == 0) { g_done1 = 0; g_done2 = 0; g_done3 = 0;
                       g_flag1 = 0; g_flag2 = 0; g_flag3 = 0; }
    }
}

// =====================================================================
// K_MLP3: sparse relu(h2) @ W3 stream (verbatim R11 champion)
// =====================================================================
__global__ void __launch_bounds__(128) k_mlp3(const float4* __restrict__ W3v) {
    __shared__ float sval[128];
    __shared__ int   sidx[128];
    __shared__ int   scnt;
    int t = threadIdx.x;
    int k0 = blockIdx.y * 120;
    if (t == 0) scnt = 0;
    __syncthreads();
    if (t < 120) {
        float h = g_h2[k0 + t];
        if (h > 0.f) {
            int p = atomicAdd(&scnt, 1);
            sidx[p] = t; sval[p] = h;
        }
    }
    __syncthreads();
    int cnt = scnt;
    int pad = (cnt + 7) & ~7;
    if (t < 8 && cnt + t < pad) {
        sidx[cnt + t] = sidx[0];
        sval[cnt + t] = 0.f;
    }
    __syncthreads();

    int c = blockIdx.x * 128 + t;
    const float4* base = W3v + (size_t)k0 * 7680 + c;
    float4 acc = make_float4(0.f, 0.f, 0.f, 0.f);
    for (int q = 0; q < cnt; q += 8) {
        int   id[8]; float hv[8]; float4 w[8];
#pragma unroll
        for (int u = 0; u < 8; u++) { id[u] = sidx[q + u]; hv[u] = sval[q + u]; }
#pragma unroll
        for (int u = 0; u < 8; u++) w[u] = __ldcs(base + (size_t)id[u] * 7680);
#pragma unroll
        for (int u = 0; u < 8; u++) {
            acc.x += hv[u] * w[u].x; acc.y += hv[u] * w[u].y;
            acc.z += hv[u] * w[u].z; acc.w += hv[u] * w[u].w;
        }
    }
    float* o = g_H + 4 * c;
    atomicAdd(o + 0, acc.x); atomicAdd(o + 1, acc.y);
    atomicAdd(o + 2, acc.z); atomicAdd(o + 3, acc.w);
}

// =====================================================================
// tail helpers
// =====================================================================
__device__ __forceinline__ void spin_flag(int* flag, int t) {
    if (t == 0) { while (*(volatile int*)flag == 0) __nanosleep(64); }
    __syncthreads();
    __threadfence();
}

// GEMM slice + last-block aggregation (R11 structure; aggregation now
// via dense 15x15 normalized-adjacency matrix M instead of 120-edge loop).
template <int L>
__device__ __forceinline__ void gcn_phase(int x, int y, int t,
                                          const float* __restrict__ W,
                                          const float* __restrict__ bias,
                                          const int* __restrict__ eidx) {
    constexpr int K     = (L == 0) ? 2048 : 1024;
    constexpr int N     = (L == 0) ? 1024 : 512;
    constexpr int KTILE = (L == 0) ? 128 : 64;
    constexpr int HALF  = KTILE / 2;
    constexpr int NY    = 16;
    constexpr int NTILE = (L == 0) ? 8 : 4;
    const float* X  = (L == 0) ? g_H  : g_X1;
    float* OUT      = (L == 0) ? g_HW1 : g_HW2;
    float* XO       = (L == 0) ? g_X1 : g_X2;
    int*   cnt      = (L == 0) ? g_cnt1 : g_cnt2;
    int*   done     = (L == 0) ? &g_done1 : &g_done2;
    int*   flag     = (L == 0) ? &g_flag1 : &g_flag2;

    __shared__ float4 Xt4[N_NODES * 32];
    float* Xt = (float*)Xt4;
    int k0 = y * KTILE;
    for (int idx = t; idx < N_NODES * (KTILE / 4); idx += 256) {
        int i = idx / (KTILE / 4), c = idx % (KTILE / 4);
        Xt4[i * 32 + c] = *(const float4*)(X + (size_t)i * K + k0 + 4 * c);
    }
    __syncthreads();

    int g  = t >> 7;
    int jt = t & 127;
    int j  = x * 128 + jt;
    const float* wp = W + (size_t)(k0 + g * HALF) * N + j;
    float acc[N_NODES];
#pragma unroll
    for (int i = 0; i < N_NODES; i++) acc[i] = 0.f;
#pragma unroll
    for (int kb = 0; kb < HALF; kb += 16) {
        float wv[16];
#pragma unroll
        for (int u = 0; u < 16; u++) wv[u] = __ldg(wp + (size_t)(kb + u) * N);
#pragma unroll
        for (int u = 0; u < 16; u++) {
            const float* xr = &Xt[g * HALF + kb + u];
#pragma unroll
            for (int i = 0; i < N_NODES; i++) acc[i] += xr[i * 128] * wv[u];
        }
    }
    __syncthreads();
    if (g == 1) {
#pragma unroll
        for (int i = 0; i < N_NODES; i++) Xt[i * 128 + jt] = acc[i];
    }
    __syncthreads();
    if (g == 0) {
#pragma unroll
        for (int i = 0; i < N_NODES; i++)
            atomicAdd(&OUT[i * N + j], acc[i] + Xt[i * 128 + jt]);
    }

    // ---- last k-split block for this x-tile aggregates ----
    __threadfence();
    __syncthreads();
    __shared__ int isLast;
    if (t == 0) isLast = (atomicAdd(&cnt[x], 1) == NY - 1);
    __syncthreads();
    if (!isLast) return;

    __shared__ int   se[NE], de[NE];
    __shared__ float degs[N_NODES], dinv[N_NODES];
    __shared__ float hws[N_NODES][128];
    __shared__ float M[N_NODES][16];       // dense normalized adjacency (dst, src)
    if (t < NE) { se[t] = eidx[t]; de[t] = eidx[NE + t]; }
    if (t < N_NODES) degs[t] = 1.f;        // self loop
    if (t < N_NODES * 16) ((float*)M)[t] = 0.f;
    __syncthreads();
    if (t < NE) atomicAdd(&degs[de[t]], 1.f);
    __syncthreads();
    if (t < N_NODES) dinv[t] = rsqrtf(degs[t]);
    __syncthreads();
    if (t < NE) atomicAdd(&M[de[t]][se[t]], dinv[se[t]] * dinv[de[t]]);
    if (t < N_NODES) atomicAdd(&M[t][t], dinv[t] * dinv[t]);
    if (t < 128) {
#pragma unroll
        for (int i = 0; i < N_NODES; i++) hws[i][t] = __ldcg(&OUT[i * N + x * 128 + t]);
    }
    __syncthreads();
    if (t < 128) {
        int jj = x * 128 + t;
        float h[N_NODES];
#pragma unroll
        for (int s = 0; s < N_NODES; s++) h[s] = hws[s][t];
        float bsv = bias[jj];
        float ssum = 0.f;
#pragma unroll
        for (int i = 0; i < N_NODES; i++) {
            float v = bsv;
#pragma unroll
            for (int s = 0; s < N_NODES; s++) v += M[i][s] * h[s];
            if (L == 0) v = fmaxf(v, 0.f);
            XO[i * N + jj] = v;
            ssum += v;
        }
        if (L == 1) g_m[jj] = ssum * (1.f / 15.f);
    }
    __threadfence();
    __syncthreads();
    if (t == 0) {
        if (atomicAdd(done, 1) == NTILE - 1) atomicExch(flag, 1);
    }
}

// =====================================================================
// K_TAIL: persistent fused gcn0 -> gcn1 -> ctx -> final (R11 structure)
// =====================================================================
__global__ void __launch_bounds__(256) k_tail(
    const float* __restrict__ gW1, const float* __restrict__ gb1,
    const float* __restrict__ gW2, const float* __restrict__ gb2,
    const float* __restrict__ attW,
    const float* __restrict__ fcW, const float* __restrict__ fcb,
    const int* __restrict__ eidx, const float* __restrict__ target,
    float* __restrict__ out) {
    int b = blockIdx.x, t = threadIdx.x;

    gcn_phase<0>(b & 7, b >> 3, t, gW1, gb1, eidx);
    if (b >= 64) return;

    spin_flag(&g_flag1, t);
    gcn_phase<1>(b & 3, b >> 2, t, gW2, gb2, eidx);
    if (b >= 32) return;

    spin_flag(&g_flag2, t);
    {
        __shared__ float sm[32];
        int k0 = (b >> 1) * 32;
        if (t < 32) sm[t] = g_m[k0 + t];
        __syncthreads();
        int j = (b & 1) * 256 + t;
        float a = 0.f;
#pragma unroll
        for (int kb = 0; kb < 32; kb += 16) {
            float wv[16];
#pragma unroll
            for (int u = 0; u < 16; u++) wv[u] = __ldg(&attW[(size_t)(k0 + kb + u) * F2 + j]);
#pragma unroll
            for (int u = 0; u < 16; u++) a += sm[kb + u] * wv[u];
        }
        atomicAdd(&g_ctx[j], a);
        __threadfence();
        __syncthreads();
        if (t == 0) {
            if (atomicAdd(&g_done3, 1) == 31) atomicExch(&g_flag3, 1);
        }
    }
    if (b != 0) return;

    spin_flag(&g_flag3, t);
    {
        __shared__ float ctx_s[F2];
        __shared__ float sc[N_NODES];
        __shared__ float lg[3];
        ctx_s[t]       = tanhf(g_ctx[t]);
        ctx_s[t + 256] = tanhf(g_ctx[t + 256]);
        if (t < 3) lg[t] = fcb[t];
        __syncthreads();

        int w = t >> 5, l = t & 31;
#pragma unroll
        for (int r = 0; r < 2; r++) {
            int n = w + 8 * r;
            if (n < N_NODES) {
                float v = 0.f;
#pragma unroll
                for (int q = 0; q < 16; q++) {
                    int j = l + 32 * q;
                    v += g_X2[n * F2 + j] * ctx_s[j];
                }
#pragma unroll
                for (int o = 16; o > 0; o >>= 1) v += __shfl_xor_sync(0xffffffffu, v, o);
                if (l == 0) sc[n] = 1.f / (1.f + expf(-v));
            }
        }
        __syncthreads();

        float p0 = 0.f, p1 = 0.f, p2 = 0.f;
#pragma unroll
        for (int r = 0; r < 2; r++) {
            int col = t + 256 * r;
            float rep = 0.f;
#pragma unroll
            for (int i = 0; i < N_NODES; i++) rep += g_X2[i * F2 + col] * sc[i];
            p0 += rep * fcW[col * 3 + 0];
            p1 += rep * fcW[col * 3 + 1];
            p2 += rep * fcW[col * 3 + 2];
        }
#pragma unroll
        for (int o = 16; o > 0; o >>= 1) {
            p0 += __shfl_xor_sync(0xffffffffu, p0, o);
            p1 += __shfl_xor_sync(0xffffffffu, p1, o);
            p2 += __shfl_xor_sync(0xffffffffu, p2, o);
        }
        if (l == 0) { atomicAdd(&lg[0], p0); atomicAdd(&lg[1], p1); atomicAdd(&lg[2], p2); }
        __syncthreads();

        if (t == 0) {
            float l0 = lg[0], l1 = lg[1], l2 = lg[2];
            float mx = fmaxf(l0, fmaxf(l1, l2));
            float e0 = expf(l0 - mx), e1 = expf(l1 - mx), e2 = expf(l2 - mx);
            float s = e0 + e1 + e2;
            float t0 = target[0], t1 = target[1], t2 = target[2];
            int cls = 0; float tm = t0;
            if (t1 > tm) { tm = t1; cls = 1; }
            if (t2 > tm) { tm = t2; cls = 2; }
            float lcls = (cls == 0) ? l0 : ((cls == 1) ? l1 : l2);
            out[0] = -(lcls - mx - logf(s));
            out[1] = e0 / s; out[2] = e1 / s; out[3] = e2 / s;
        }
    }
}

// ---------- host ----------
extern "C" void kernel_launch(void* const* d_in, const int* in_sizes, int n_in,
                              void* d_out, int out_size) {
    const float* f      = (const float*)d_in[0];
    const int*   eidx   = (const int*)  d_in[1];
    const float* target = (const float*)d_in[2];
    const float* W1     = (const float*)d_in[3];
    const float* b1     = (const float*)d_in[4];
    const float* W2     = (const float*)d_in[5];
    const float* b2     = (const float*)d_in[6];
    const float* W3     = (const float*)d_in[7];
    const float* b3     = (const float*)d_in[8];
    const float* gW1    = (const float*)d_in[9];
    const float* gb1    = (const float*)d_in[10];
    const float* gW2    = (const float*)d_in[11];
    const float* gb2    = (const float*)d_in[12];
    const float* attW   = (const float*)d_in[13];
    const float* fcW    = (const float*)d_in[14];
    const float* fcb    = (const float*)d_in[15];
    float* out = (float*)d_out;

    k_pre <<<148, 256>>>(f, W1, b1, W2, b2, b3);
    k_mlp3<<<dim3(60, 16), 128>>>((const float4*)W3);
    k_tail<<<128, 256>>>(gW1, gb1, gW2, gb2, attW, fcW, fcb, eidx, target, out);
}

// round 17
// speedup vs baseline: 1.2145x; 1.0068x over previous
#include <cuda_runtime.h>
#include <math.h>

#define N_NODES 15
#define EMBED   2048
#define F1      1024
#define F2      512
#define NE      120
#define H1N     480
#define H2N     1920
#define HN      (N_NODES*EMBED)   // 30720

// ---------- scratch (device globals) ----------
__device__ float g_h2[H2N];
__device__ float g_H[HN];
__device__ float g_HW1[N_NODES*F1];
__device__ float g_X1[N_NODES*F1];
__device__ float g_HW2[N_NODES*F2];
__device__ float g_X2[N_NODES*F2];
__device__ float g_m[F2];
__device__ float g_ctx[F2];
__device__ int   g_cnt1[8], g_cnt2[4];
__device__ int   g_t1f[8];             // per-gcn0-tile "X1 ready" flags
__device__ int   g_done2, g_done3;
__device__ int   g_flag2, g_flag3;

// =====================================================================
// K_PRE (512 thr): blocks 0..119: MLP1 (1 wave) + MLP2 (16 cols x 32 kgrp,
//                  one 15-deep wave).  blocks 120..147: inits + reset.
// =====================================================================
__global__ void __launch_bounds__(512) k_pre(
    const float* __restrict__ f,  const float* __restrict__ W1, const float* __restrict__ b1,
    const float* __restrict__ W2, const float* __restrict__ b2, const float* __restrict__ b3) {
    int bx = blockIdx.x, t = threadIdx.x;
    if (bx < 120) {
        __shared__ float sf[N_NODES];
        __shared__ float sh1[H1N];
        __shared__ float red[32][16];
        if (t < N_NODES) sf[t] = f[t];
        __syncthreads();
        if (t < H1N) {                     // MLP1: one 15-deep wave
            float wv[N_NODES];
#pragma unroll
            for (int i = 0; i < N_NODES; i++) wv[i] = __ldg(&W1[i * H1N + t]);
            float a = b1[t];
#pragma unroll
            for (int i = 0; i < N_NODES; i++) a += sf[i] * wv[i];
            sh1[t] = fmaxf(a, 0.f);
        }
        __syncthreads();
        // MLP2: 16 cols x 32 kgrps of 15 -> one 15-deep wave
        int col = bx * 16 + (t & 15);
        int kg  = t >> 4;                  // 0..31
        int k0  = kg * 15;
        float wv[15];
#pragma unroll
        for (int u = 0; u < 15; u++) wv[u] = __ldg(&W2[(size_t)(k0 + u) * H2N + col]);
        float a = 0.f;
#pragma unroll
        for (int u = 0; u < 15; u++) a += sh1[k0 + u] * wv[u];
        red[kg][t & 15] = a;
        __syncthreads();
        if (t < 16) {
            int c = bx * 16 + t;
            float v = b2[c];
#pragma unroll
            for (int s2 = 0; s2 < 32; s2++) v += red[s2][t];
            g_h2[c] = fmaxf(v, 0.f);
        }
    } else {
        int gt = (bx - 120) * 512 + t;     // 0 .. 14335
        const int GS = 28 * 512;
#pragma unroll 3
        for (int i = gt; i < HN; i += GS)           g_H[i]   = b3[i];
#pragma unroll 2
        for (int i = gt; i < N_NODES * F1; i += GS) g_HW1[i] = 0.f;
        if (gt < N_NODES * F2)                      g_HW2[gt] = 0.f;
        if (gt < F2) g_ctx[gt] = 0.f;
        if (gt < 8)  { g_cnt1[gt] = 0; g_t1f[gt] = 0; }
        if (gt < 4)    g_cnt2[gt] = 0;
        if (gt == 0) { g_done2 = 0; g_done3 = 0; g_flag2 = 0; g_flag3 = 0; }
    }
}

// =====================================================================
// K_MLP3: sparse relu(h2) @ W3 stream (verbatim champion)
// =====================================================================
__global__ void __launch_bounds__(128) k_mlp3(const float4* __restrict__ W3v) {
    __shared__ float sval[128];
    __shared__ int   sidx[128];
    __shared__ int   scnt;
    int t = threadIdx.x;
    int k0 = blockIdx.y * 120;
    if (t == 0) scnt = 0;
    __syncthreads();
    if (t < 120) {
        float h = g_h2[k0 + t];
        if (h > 0.f) {
            int p = atomicAdd(&scnt, 1);
            sidx[p] = t; sval[p] = h;
        }
    }
    __syncthreads();
    int cnt = scnt;
    int pad = (cnt + 7) & ~7;
    if (t < 8 && cnt + t < pad) {
        sidx[cnt + t] = sidx[0];
        sval[cnt + t] = 0.f;
    }
    __syncthreads();

    int c = blockIdx.x * 128 + t;
    const float4* base = W3v + (size_t)k0 * 7680 + c;
    float4 acc = make_float4(0.f, 0.f, 0.f, 0.f);
    for (int q = 0; q < cnt; q += 8) {
        int   id[8]; float hv[8]; float4 w[8];
#pragma unroll
        for (int u = 0; u < 8; u++) { id[u] = sidx[q + u]; hv[u] = sval[q + u]; }
#pragma unroll
        for (int u = 0; u < 8; u++) w[u] = __ldcs(base + (size_t)id[u] * 7680);
#pragma unroll
        for (int u = 0; u < 8; u++) {
            acc.x += hv[u] * w[u].x; acc.y += hv[u] * w[u].y;
            acc.z += hv[u] * w[u].z; acc.w += hv[u] * w[u].w;
        }
    }
    float* o = g_H + 4 * c;
    atomicAdd(o + 0, acc.x); atomicAdd(o + 1, acc.y);
    atomicAdd(o + 2, acc.z); atomicAdd(o + 3, acc.w);
}

// =====================================================================
// tail helpers
// =====================================================================
__device__ __forceinline__ void spin_flag(int* flag, int t) {
    if (t == 0) { while (*(volatile int*)flag == 0) __nanosleep(64); }
    __syncthreads();
    __threadfence();
}

// GEMM slice + last-block aggregation via dense 15x15 M (R16 champion body;
// completion signaling: L=0 -> per-tile g_t1f[x], L=1 -> done2/flag2).
template <int L>
__device__ __forceinline__ void gcn_phase(int x, int y, int t,
                                          const float* __restrict__ W,
                                          const float* __restrict__ bias,
                                          const int* __restrict__ eidx) {
    constexpr int K     = (L == 0) ? 2048 : 1024;
    constexpr int N     = (L == 0) ? 1024 : 512;
    constexpr int KTILE = (L == 0) ? 128 : 64;
    constexpr int HALF  = KTILE / 2;
    constexpr int NY    = 16;
    const float* X  = (L == 0) ? g_H  : g_X1;
    float* OUT      = (L == 0) ? g_HW1 : g_HW2;
    float* XO       = (L == 0) ? g_X1 : g_X2;
    int*   cnt      = (L == 0) ? g_cnt1 : g_cnt2;

    __shared__ float4 Xt4[N_NODES * 32];
    float* Xt = (float*)Xt4;
    int k0 = y * KTILE;
    for (int idx = t; idx < N_NODES * (KTILE / 4); idx += 256) {
        int i = idx / (KTILE / 4), c = idx % (KTILE / 4);
        Xt4[i * 32 + c] = *(const float4*)(X + (size_t)i * K + k0 + 4 * c);
    }
    __syncthreads();

    int g  = t >> 7;
    int jt = t & 127;
    int j  = x * 128 + jt;
    const float* wp = W + (size_t)(k0 + g * HALF) * N + j;
    float acc[N_NODES];
#pragma unroll
    for (int i = 0; i < N_NODES; i++) acc[i] = 0.f;
#pragma unroll
    for (int kb = 0; kb < HALF; kb += 16) {
        float wv[16];
#pragma unroll
        for (int u = 0; u < 16; u++) wv[u] = __ldg(wp + (size_t)(kb + u) * N);
#pragma unroll
        for (int u = 0; u < 16; u++) {
            const float* xr = &Xt[g * HALF + kb + u];
#pragma unroll
            for (int i = 0; i < N_NODES; i++) acc[i] += xr[i * 128] * wv[u];
        }
    }
    __syncthreads();
    if (g == 1) {
#pragma unroll
        for (int i = 0; i < N_NODES; i++) Xt[i * 128 + jt] = acc[i];
    }
    __syncthreads();
    if (g == 0) {
#pragma unroll
        for (int i = 0; i < N_NODES; i++)
            atomicAdd(&OUT[i * N + j], acc[i] + Xt[i * 128 + jt]);
    }

    // ---- last k-split block for this x-tile aggregates ----
    __threadfence();
    __syncthreads();
    __shared__ int isLast;
    if (t == 0) isLast = (atomicAdd(&cnt[x], 1) == NY - 1);
    __syncthreads();
    if (!isLast) return;

    __shared__ int   se[NE], de[NE];
    __shared__ float degs[N_NODES], dinv[N_NODES];
    __shared__ float hws[N_NODES][128];
    __shared__ float M[N_NODES][16];       // dense normalized adjacency (dst, src)
    if (t < NE) { se[t] = eidx[t]; de[t] = eidx[NE + t]; }
    if (t < N_NODES) degs[t] = 1.f;        // self loop
    if (t < N_NODES * 16) ((float*)M)[t] = 0.f;
    __syncthreads();
    if (t < NE) atomicAdd(&degs[de[t]], 1.f);
    __syncthreads();
    if (t < N_NODES) dinv[t] = rsqrtf(degs[t]);
    __syncthreads();
    if (t < NE) atomicAdd(&M[de[t]][se[t]], dinv[se[t]] * dinv[de[t]]);
    if (t < N_NODES) atomicAdd(&M[t][t], dinv[t] * dinv[t]);
    if (t < 128) {
#pragma unroll
        for (int i = 0; i < N_NODES; i++) hws[i][t] = __ldcg(&OUT[i * N + x * 128 + t]);
    }
    __syncthreads();
    if (t < 128) {
        int jj = x * 128 + t;
        float h[N_NODES];
#pragma unroll
        for (int s = 0; s < N_NODES; s++) h[s] = hws[s][t];
        float bsv = bias[jj];
        float ssum = 0.f;
#pragma unroll
        for (int i = 0; i < N_NODES; i++) {
            float v = bsv;
#pragma unroll
            for (int s = 0; s < N_NODES; s++) v += M[i][s] * h[s];
            if (L == 0) v = fmaxf(v, 0.f);
            XO[i * N + jj] = v;
            ssum += v;
        }
        if (L == 1) g_m[jj] = ssum * (1.f / 15.f);
    }
    __threadfence();
    __syncthreads();
    if (t == 0) {
        if (L == 0) {
            atomicExch(&g_t1f[x], 1);                       // per-tile ready
        } else {
            if (atomicAdd(&g_done2, 1) == 3) atomicExch(&g_flag2, 1);
        }
    }
}

// =====================================================================
// K_TAIL: gcn0 -> (per-tile flags) gcn1 -> ctx -> final
// =====================================================================
__global__ void __launch_bounds__(256) k_tail(
    const float* __restrict__ gW1, const float* __restrict__ gb1,
    const float* __restrict__ gW2, const float* __restrict__ gb2,
    const float* __restrict__ attW,
    const float* __restrict__ fcW, const float* __restrict__ fcb,
    const int* __restrict__ eidx, const float* __restrict__ target,
    float* __restrict__ out) {
    int b = blockIdx.x, t = threadIdx.x;

    // ---- phase 1: GCN layer 0 (128 blocks: 8 x-tiles x 16 ksplit) ----
    gcn_phase<0>(b & 7, b >> 3, t, gW1, gb1, eidx);
    if (b >= 64) return;

    // ---- phase 2: GCN layer 1 (64 blocks: 4 x x 16 y); each y-split
    //      needs only gcn0 tile (y>>1) -> per-tile spin, early start ----
    {
        int y = b >> 2;
        spin_flag(&g_t1f[y >> 1], t);
        gcn_phase<1>(b & 3, y, t, gW2, gb2, eidx);
    }
    if (b >= 32) return;

    // ---- phase 3: ctx = m @ attW (32 blocks: 2 col x 16 ksplit) ----
    spin_flag(&g_flag2, t);
    {
        __shared__ float sm[32];
        int k0 = (b >> 1) * 32;
        if (t < 32) sm[t] = g_m[k0 + t];
        __syncthreads();
        int j = (b & 1) * 256 + t;
        float a = 0.f;
#pragma unroll
        for (int kb = 0; kb < 32; kb += 16) {
            float wv[16];
#pragma unroll
            for (int u = 0; u < 16; u++) wv[u] = __ldg(&attW[(size_t)(k0 + kb + u) * F2 + j]);
#pragma unroll
            for (int u = 0; u < 16; u++) a += sm[kb + u] * wv[u];
        }
        atomicAdd(&g_ctx[j], a);
        __threadfence();
        __syncthreads();
        if (t == 0) {
            if (atomicAdd(&g_done3, 1) == 31) atomicExch(&g_flag3, 1);
        }
    }
    if (b != 0) return;

    // ---- phase 4: attention pool + fc + softmax + loss ----
    spin_flag(&g_flag3, t);
    {
        __shared__ float ctx_s[F2];
        __shared__ float sc[N_NODES];
        __shared__ float lg[3];
        ctx_s[t]       = tanhf(g_ctx[t]);
        ctx_s[t + 256] = tanhf(g_ctx[t + 256]);
        if (t < 3) lg[t] = fcb[t];
        __syncthreads();

        int w = t >> 5, l = t & 31;
#pragma unroll
        for (int r = 0; r < 2; r++) {
            int n = w + 8 * r;
            if (n < N_NODES) {
                float v = 0.f;
#pragma unroll
                for (int q = 0; q < 16; q++) {
                    int j = l + 32 * q;
                    v += g_X2[n * F2 + j] * ctx_s[j];
                }
#pragma unroll
                for (int o = 16; o > 0; o >>= 1) v += __shfl_xor_sync(0xffffffffu, v, o);
                if (l == 0) sc[n] = 1.f / (1.f + expf(-v));
            }
        }
        __syncthreads();

        float p0 = 0.f, p1 = 0.f, p2 = 0.f;
#pragma unroll
        for (int r = 0; r < 2; r++) {
            int col = t + 256 * r;
            float rep = 0.f;
#pragma unroll
            for (int i = 0; i < N_NODES; i++) rep += g_X2[i * F2 + col] * sc[i];
            p0 += rep * fcW[col * 3 + 0];
            p1 += rep * fcW[col * 3 + 1];
            p2 += rep * fcW[col * 3 + 2];
        }
#pragma unroll
        for (int o = 16; o > 0; o >>= 1) {
            p0 += __shfl_xor_sync(0xffffffffu, p0, o);
            p1 += __shfl_xor_sync(0xffffffffu, p1, o);
            p2 += __shfl_xor_sync(0xffffffffu, p2, o);
        }
        if (l == 0) { atomicAdd(&lg[0], p0); atomicAdd(&lg[1], p1); atomicAdd(&lg[2], p2); }
        __syncthreads();

        if (t == 0) {
            float l0 = lg[0], l1 = lg[1], l2 = lg[2];
            float mx = fmaxf(l0, fmaxf(l1, l2));
            float e0 = expf(l0 - mx), e1 = expf(l1 - mx), e2 = expf(l2 - mx);
            float s = e0 + e1 + e2;
            float t0 = target[0], t1 = target[1], t2 = target[2];
            int cls = 0; float tm = t0;
            if (t1 > tm) { tm = t1; cls = 1; }
            if (t2 > tm) { tm = t2; cls = 2; }
            float lcls = (cls == 0) ? l0 : ((cls == 1) ? l1 : l2);
            out[0] = -(lcls - mx - logf(s));
            out[1] = e0 / s; out[2] = e1 / s; out[3] = e2 / s;
        }
    }
}

// ---------- host ----------
extern "C" void kernel_launch(void* const* d_in, const int* in_sizes, int n_in,
                              void* d_out, int out_size) {
    const float* f      = (const float*)d_in[0];
    const int*   eidx   = (const int*)  d_in[1];
    const float* target = (const float*)d_in[2];
    const float* W1     = (const float*)d_in[3];
    const float* b1     = (const float*)d_in[4];
    const float* W2     = (const float*)d_in[5];
    const float* b2     = (const float*)d_in[6];
    const float* W3     = (const float*)d_in[7];
    const float* b3     = (const float*)d_in[8];
    const float* gW1    = (const float*)d_in[9];
    const float* gb1    = (const float*)d_in[10];
    const float* gW2    = (const float*)d_in[11];
    const float* gb2    = (const float*)d_in[12];
    const float* attW   = (const float*)d_in[13];
    const float* fcW    = (const float*)d_in[14];
    const float* fcb    = (const float*)d_in[15];
    float* out = (float*)d_out;

    k_pre <<<148, 512>>>(f, W1, b1, W2, b2, b3);
    k_mlp3<<<dim3(60, 16), 128>>>((const float4*)W3);
    k_tail<<<128, 256>>>(gW1, gb1, gW2, gb2, attW, fcW, fcb, eidx, target, out);
}